// round 7
// baseline (speedup 1.0000x reference)
#include <cuda_runtime.h>
#include <cstdint>

#define B_  2048
#define T_  336
#define F_  10
#define H1_ 70
#define H2_ 21
#define D1_ 30
#define D2_ 20

typedef unsigned long long u64;

// ---------------- scratch (__device__ globals; no allocations) ----------------
__device__ float g_xT [(size_t)T_ * B_ * F_];          // x transposed [T][B][10]
__device__ float g_h1 [(size_t)T_ * B_ * (2*H1_)];     // layer1 out   [T][B][140]
__device__ float g_xg2[(size_t)T_ * B_ * (8*H2_)];     // layer2 input gates [T][B][168]
__device__ float g_h2 [(size_t)T_ * B_ * (2*H2_)];     // layer2 out   [T][B][42]
__device__ float g_y  [(size_t)T_ * B_];               // head out, t-major
__device__ float g_w2t[140 * 168];                     // W2_ih^T packed, both dirs
__device__ float g_b2 [168];

// ---------------- packed f32x2 fma ----------------
__device__ __forceinline__ u64 fma2_(u64 a, u64 b, u64 c) {
    u64 d;
    asm("fma.rn.f32x2 %0, %1, %2, %3;" : "=l"(d) : "l"(a), "l"(b), "l"(c));
    return d;
}

// ---------------- activations (accurate fast-math, ~1e-6 rel) ----------------
__device__ __forceinline__ float fsigm(float x) {
    return __fdividef(1.f, 1.f + __expf(-x));
}
__device__ __forceinline__ float ftanh_(float x) {
    return 1.f - 2.f * __fdividef(1.f, 1.f + __expf(2.f * x));
}

// ---------------- transpose x: [B][T][F] -> [T][B][F] ----------------
__global__ void transpose_x(const float* __restrict__ x) {
    int gid = blockIdx.x * blockDim.x + threadIdx.x;
    if (gid < B_ * T_ * F_) {
        int f = gid % F_;
        int t = (gid / F_) % T_;
        int b = gid / (F_ * T_);
        g_xT[((size_t)t * B_ + b) * F_ + f] = x[gid];
    }
}

// ---------------- prep: transpose layer-2 input weights to k-major ----------------
__global__ void prep_w2(const float* __restrict__ wf, const float* __restrict__ wb,
                        const float* __restrict__ bfi, const float* __restrict__ bfh,
                        const float* __restrict__ bbi, const float* __restrict__ bbh) {
    int i = blockIdx.x * blockDim.x + threadIdx.x;
    if (i < 168 * 140) {
        int jj = i / 140;
        int k  = i % 140;
        int dir = jj / 84, j = jj % 84;
        const float* w = dir ? wb : wf;
        g_w2t[k * 168 + jj] = w[j * 140 + k];
    }
    if (i < 168) {
        int dir = i / 84, j = i % 84;
        g_b2[i] = dir ? (bbi[j] + bbh[j]) : (bfi[j] + bfh[j]);
    }
}

// ================= layer 1: fused-input recurrent LSTM, 3 K-teams =================
// block = 32 samples x 1 dir; K padded to 84 (row 80 = bias, a=1; 81-83 zero).
// 864 threads = 3 K-teams x (4 SG x 70 chunks) = 840 active matvec workers.
__global__ __launch_bounds__(864, 1)
void lstm1_kernel(const float* __restrict__ Wih_f, const float* __restrict__ Whh_f,
                  const float* __restrict__ bih_f, const float* __restrict__ bhh_f,
                  const float* __restrict__ Wih_b, const float* __restrict__ Whh_b,
                  const float* __restrict__ bih_b, const float* __restrict__ bhh_b)
{
    constexpr int I = 10, H = 70, KPAD = 84, KP2 = 84, G = 280, GP = 280;
    constexpr int NJC = 70, TB = 8, NTH = 864, KH = 28, NTEAM = 3;
    extern __shared__ float sm[];
    float* sW = sm;                      // [84][280] k-major (row 80 = bias)
    float* gP = sW + KPAD * GP;          // [3][32][280] partial gates
    float* aS = gP + NTEAM * 32 * GP;    // [32][84] duplicated pairs (float2)
    float* cS = aS + 32 * KP2 * 2;       // [32][70]

    const int dir = blockIdx.y;
    const float* Wih = dir ? Wih_b : Wih_f;
    const float* Whh = dir ? Whh_b : Whh_f;
    const float* bih = dir ? bih_b : bih_f;
    const float* bhh = dir ? bhh_b : bhh_f;
    const int b0  = blockIdx.x * 32;
    const int tid = threadIdx.x;

    for (int idx = tid; idx < KPAD * GP; idx += NTH) {
        int k = idx / GP, j = idx % GP;
        float v = 0.f;
        if (k < I)       v = Wih[j * I + k];
        else if (k < 80) v = Whh[j * H + (k - I)];
        else if (k == 80) v = bih[j] + bhh[j];
        sW[idx] = v;
    }
    for (int idx = tid; idx < 32 * KP2 * 2; idx += NTH) aS[idx] = 0.f;
    for (int idx = tid; idx < 32 * H; idx += NTH) cS[idx] = 0.f;
    __syncthreads();
    if (tid < 32) ((float2*)aS)[tid * KP2 + 80] = make_float2(1.f, 1.f);  // bias lane

    // x staging map: 320 floats, tid<320 one each (stride-1 dup-pair stores)
    const bool xp = tid < 32 * I;
    const int xb0 = tid / I, xk0 = tid % I;
    // activation map start: stride NTH=864 -> b += 12, h += 24
    const int ab0 = tid / H, ah0 = tid % H;

    const int ks = tid / (4 * NJC);                 // K-team (840 active)
    const int rr = tid - ks * (4 * NJC);
    const int sg = rr / NJC, jc = rr % NJC;
    const bool mv = tid < NTEAM * 4 * NJC;
    const int kbase = ks * KH;
    const u64* arow = ((const u64*)aS) + (size_t)(sg * TB) * KP2;
    const ulonglong2* sWp = (const ulonglong2*)sW;
    ulonglong2* gPd = (ulonglong2*)(gP + ks * 32 * GP);

    int t = dir ? (T_ - 1) : 0;
    const int tstep = dir ? -1 : 1;
    float xp0 = 0.f;
    if (xp) xp0 = g_xT[((size_t)t * B_ + b0) * I + tid];
    __syncthreads();

    for (int s = 0; s < T_; ++s, t += tstep) {
        // ---- stage x_t as duplicated pairs ----
        if (xp) ((float2*)aS)[xb0 * KP2 + xk0] = make_float2(xp0, xp0);
        __syncthreads();
        if (xp && s + 1 < T_)
            xp0 = g_xT[((size_t)(t + tstep) * B_ + b0) * I + tid];

        // ---- packed matvec partial over k in [kbase, kbase+28) ----
        if (mv) {
            ulonglong2 acc[TB];
            #pragma unroll
            for (int r = 0; r < TB; ++r) acc[r] = make_ulonglong2(0ull, 0ull);

            #pragma unroll 2
            for (int kk = 0; kk < KH; kk += 2) {
                const int k = kbase + kk;
                ulonglong2 w0 = sWp[k * NJC + jc];
                ulonglong2 w1 = sWp[(k + 1) * NJC + jc];
                #pragma unroll
                for (int r = 0; r < TB; ++r) {
                    ulonglong2 a = *(const ulonglong2*)(arow + r * KP2 + k);
                    acc[r].x = fma2_(a.x, w0.x, acc[r].x);
                    acc[r].y = fma2_(a.x, w0.y, acc[r].y);
                    acc[r].x = fma2_(a.y, w1.x, acc[r].x);
                    acc[r].y = fma2_(a.y, w1.y, acc[r].y);
                }
            }
            #pragma unroll
            for (int r = 0; r < TB; ++r) gPd[(sg * TB + r) * NJC + jc] = acc[r];
        }
        __syncthreads();

        // ---- gates: sum 3 partials + state update + h store ----
        {
            float* orow = g_h1 + ((size_t)t * B_ + b0) * (2 * H1_) + dir * H;
            int b = ab0, h = ah0;
            for (int e = tid; e < 32 * H; e += NTH) {
                const float* g0 = gP + b * GP;
                const float* g1 = g0 + 32 * GP;
                const float* g2 = g1 + 32 * GP;
                float gi = g0[h]         + g1[h]         + g2[h];
                float gf = g0[H + h]     + g1[H + h]     + g2[H + h];
                float gg = g0[2 * H + h] + g1[2 * H + h] + g2[2 * H + h];
                float go = g0[3 * H + h] + g1[3 * H + h] + g2[3 * H + h];
                float c = fsigm(gf) * cS[e] + fsigm(gi) * ftanh_(gg);
                cS[e] = c;
                float hn = fsigm(go) * ftanh_(c);
                ((float2*)aS)[b * KP2 + I + h] = make_float2(hn, hn);
                orow[b * (2 * H1_) + h] = hn;
                b += 12; h += 24; if (h >= H) { h -= H; ++b; }
            }
        }
    }
}

// ================= layer-2 input GEMM: xg2 = h1 @ W2ih^T + biases, 2 K-teams =================
// block = 64 rows; K padded to 144 (row 140 = bias, 141-143 zero);
// 672 threads = 2 teams x (8 SG x 42 chunks). Team1 -> partials; team0 adds + stores.
__global__ __launch_bounds__(672, 1)
void xg2_kernel()
{
    constexpr int BB = 64, KPAD = 144, KP2 = 144, G = 168, NJC = 42, TB = 8, KH = 72, NTH = 672;
    extern __shared__ float sm[];
    float* sW = sm;                 // [144][168]
    float* aS = sW + KPAD * G;      // [64][144] duplicated pairs
    float* gP = aS + BB * KP2 * 2;  // [64][168] team1 partial
    const int tid = threadIdx.x;
    const size_t row0 = (size_t)blockIdx.x * BB;

    for (int idx = tid; idx < KPAD * G; idx += NTH) {
        int k = idx / G, j = idx % G;
        float v = 0.f;
        if (k < 140)      v = g_w2t[idx];
        else if (k == 140) v = g_b2[j];
        sW[idx] = v;
    }
    {
        const float* src = g_h1 + row0 * 140;
        int r = tid / 140, c = tid % 140;
        for (int q = tid; q < BB * 140; q += NTH) {
            float v = src[q];
            ((float2*)aS)[r * KP2 + c] = make_float2(v, v);
            r += 4; c += 112; if (c >= 140) { c -= 140; ++r; }
        }
        if (tid < BB * 4) {
            int b = tid / 4, k = 140 + tid % 4;
            ((float2*)aS)[b * KP2 + k] = make_float2(k == 140 ? 1.f : 0.f,
                                                     k == 140 ? 1.f : 0.f);
        }
    }
    __syncthreads();

    {
        const int ks = tid / 336;
        const int rr = tid - ks * 336;
        const int sg = rr / NJC, jc = rr % NJC;
        const int kbase = ks * KH;
        const u64* arow = ((const u64*)aS) + (size_t)(sg * TB) * KP2;
        const ulonglong2* sWp = (const ulonglong2*)sW;
        ulonglong2 acc[TB];
        #pragma unroll
        for (int r = 0; r < TB; ++r) acc[r] = make_ulonglong2(0ull, 0ull);

        #pragma unroll 2
        for (int kk = 0; kk < KH; kk += 2) {
            const int k = kbase + kk;
            ulonglong2 w0 = sWp[k * NJC + jc];
            ulonglong2 w1 = sWp[(k + 1) * NJC + jc];
            #pragma unroll
            for (int r = 0; r < TB; ++r) {
                ulonglong2 a = *(const ulonglong2*)(arow + r * KP2 + k);
                acc[r].x = fma2_(a.x, w0.x, acc[r].x);
                acc[r].y = fma2_(a.x, w0.y, acc[r].y);
                acc[r].x = fma2_(a.y, w1.x, acc[r].x);
                acc[r].y = fma2_(a.y, w1.y, acc[r].y);
            }
        }

        float4* gPd = (float4*)gP;
        if (ks == 1) {
            #pragma unroll
            for (int r = 0; r < TB; ++r)
                gPd[(sg * TB + r) * NJC + jc] = *reinterpret_cast<float4*>(&acc[r]);
        }
        __syncthreads();
        if (ks == 0) {
            float4* outp = (float4*)(g_xg2 + row0 * G);
            #pragma unroll
            for (int r = 0; r < TB; ++r) {
                float4 p = gPd[(sg * TB + r) * NJC + jc];
                float4 m = *reinterpret_cast<float4*>(&acc[r]);
                m.x += p.x; m.y += p.y; m.z += p.z; m.w += p.w;
                outp[(sg * TB + r) * NJC + jc] = m;
            }
        }
    }
}

// ================= layer 2: recurrent-only LSTM (K=21 pad 24), K-split teams =================
__global__ __launch_bounds__(384, 1)
void lstm2_kernel(const float* __restrict__ Whh_f, const float* __restrict__ Whh_b)
{
    constexpr int H = 21, KPAD = 24, KP2 = 24, G = 84, GP = 96;
    constexpr int NJC = 24, TB = 4, NTH = 384, KH = 12;
    extern __shared__ float sm[];
    float* sW = sm;                 // [24][96]
    float* gS = sW + KPAD * GP;     // [2][32][96] input gates (double-buffered), team0 rmw
    float* gP = gS + 2 * 32 * GP;   // [32][96] team1 partial
    float* aS = gP + 32 * GP;       // [32][24] duplicated pairs
    float* cS = aS + 32 * KP2 * 2;  // [32][21]

    const int dir = blockIdx.y;
    const float* Whh = dir ? Whh_b : Whh_f;
    const int b0  = blockIdx.x * 32;
    const int tid = threadIdx.x;

    for (int idx = tid; idx < KPAD * GP; idx += NTH) {
        int k = idx / GP, j = idx % GP;
        sW[idx] = (k < H && j < G) ? Whh[j * H + k] : 0.f;
    }
    for (int idx = tid; idx < 32 * KP2 * 2; idx += NTH) aS[idx] = 0.f;
    for (int idx = tid; idx < 32 * H; idx += NTH) cS[idx] = 0.f;

    const int gb0 = tid / 21, gc0 = tid % 21;
    const int i1 = tid + NTH;
    const int gb1 = i1 / 21, gc1 = i1 % 21;
    const bool v1 = i1 < 672;
    const int ab0 = tid / H, ah0 = tid % H;

    const int ks = tid / 192;
    const int r192 = tid - ks * 192;
    const int sg = r192 / NJC, jc = r192 % NJC;
    const int kbase = ks * KH;
    const u64* arow = ((const u64*)aS) + (size_t)(sg * TB) * KP2;
    const ulonglong2* sWp = (const ulonglong2*)sW;

    int t = dir ? (T_ - 1) : 0;
    const int tstep = dir ? -1 : 1;
    float4 gp0, gp1;
    {
        const float4* src = (const float4*)(g_xg2 + ((size_t)t * B_ + b0) * 168 + dir * 84);
        gp0 = src[gb0 * 42 + gc0];
        if (v1) gp1 = src[gb1 * 42 + gc1];
    }
    __syncthreads();

    for (int s = 0; s < T_; ++s, t += tstep) {
        const int p = s & 1;
        float* gSb = gS + p * 32 * GP;
        float4* gSd = (float4*)gSb;
        gSd[gb0 * 24 + gc0] = gp0;
        if (v1) gSd[gb1 * 24 + gc1] = gp1;
        __syncthreads();
        if (s + 1 < T_) {
            const float4* src = (const float4*)(g_xg2 + ((size_t)(t + tstep) * B_ + b0) * 168 + dir * 84);
            gp0 = src[gb0 * 42 + gc0];
            if (v1) gp1 = src[gb1 * 42 + gc1];
        }
        {
            ulonglong2* dst = (ulonglong2*)(ks ? gP : gSb);
            ulonglong2 acc[TB];
            #pragma unroll
            for (int r = 0; r < TB; ++r) {
                if (ks == 0) acc[r] = ((const ulonglong2*)gSb)[(sg * TB + r) * NJC + jc];
                else         acc[r] = make_ulonglong2(0ull, 0ull);
            }
            #pragma unroll
            for (int kk = 0; kk < KH; kk += 2) {
                const int k = kbase + kk;
                ulonglong2 w0 = sWp[k * NJC + jc];
                ulonglong2 w1 = sWp[(k + 1) * NJC + jc];
                #pragma unroll
                for (int r = 0; r < TB; ++r) {
                    ulonglong2 a = *(const ulonglong2*)(arow + r * KP2 + k);
                    acc[r].x = fma2_(a.x, w0.x, acc[r].x);
                    acc[r].y = fma2_(a.x, w0.y, acc[r].y);
                    acc[r].x = fma2_(a.y, w1.x, acc[r].x);
                    acc[r].y = fma2_(a.y, w1.y, acc[r].y);
                }
            }
            #pragma unroll
            for (int r = 0; r < TB; ++r)
                dst[(sg * TB + r) * NJC + jc] = acc[r];
        }
        __syncthreads();

        {
            float* orow = g_h2 + ((size_t)t * B_ + b0) * (2 * H2_) + dir * H;
            int b = ab0, h = ah0;
            for (int e = tid; e < 32 * H; e += NTH) {
                const float* g0 = gSb + b * GP;
                const float* g1 = gP + b * GP;
                float gi = g0[h]         + g1[h];
                float gf = g0[H + h]     + g1[H + h];
                float gg = g0[2 * H + h] + g1[2 * H + h];
                float go = g0[3 * H + h] + g1[3 * H + h];
                float c = fsigm(gf) * cS[e] + fsigm(gi) * ftanh_(gg);
                cS[e] = c;
                float hn = fsigm(go) * ftanh_(c);
                ((float2*)aS)[b * KP2 + h] = make_float2(hn, hn);
                orow[b * (2 * H2_) + h] = hn;
                b += 18; h += 6; if (h >= H) { h -= H; ++b; }
            }
        }
    }
}

// ================= dense head (smem-staged rows, padded pitch) =================
__global__ __launch_bounds__(256)
void dense_kernel(const float* __restrict__ wd1, const float* __restrict__ bd1,
                  const float* __restrict__ wd2, const float* __restrict__ bd2,
                  const float* __restrict__ wo,  const float* __restrict__ bo)
{
    constexpr int IN = 2 * H2_;   // 42
    constexpr int INP = 43;       // padded pitch (odd -> conflict-free)
    extern __shared__ float sm[];
    float* sIn = sm;                    // [256][43]
    float* s1  = sIn + 256 * INP;       // [30][42]
    float* sb1 = s1 + D1_ * IN;
    float* s2  = sb1 + D1_;             // [20][30]
    float* sb2 = s2 + D2_ * D1_;
    float* sWo = sb2 + D2_;
    float* sBo = sWo + D2_;

    const int tid = threadIdx.x;
    const size_t row0 = (size_t)blockIdx.x * 256;

    {
        const float* src = g_h2 + row0 * IN;
        int r = tid / IN, c = tid % IN;
        for (int q = tid; q < 256 * IN; q += 256) {
            sIn[r * INP + c] = src[q];
            r += 6; c += 4; if (c >= IN) { c -= IN; ++r; }
        }
    }
    for (int i = tid; i < D1_ * IN; i += 256) s1[i] = wd1[i];
    for (int i = tid; i < D2_ * D1_; i += 256) s2[i] = wd2[i];
    if (tid < D1_) sb1[tid] = bd1[tid];
    if (tid < D2_) { sb2[tid] = bd2[tid]; sWo[tid] = wo[tid]; }
    if (tid == 0) sBo[0] = bo[0];
    __syncthreads();

    const float* in = sIn + tid * INP;
    float acc2[D2_];
    #pragma unroll
    for (int k = 0; k < D2_; ++k) acc2[k] = sb2[k];
    #pragma unroll 2
    for (int j = 0; j < D1_; ++j) {
        float v = sb1[j];
        #pragma unroll
        for (int k = 0; k < IN; ++k) v = fmaf(in[k], s1[j * IN + k], v);
        v = fmaxf(v, 0.f);
        #pragma unroll
        for (int k = 0; k < D2_; ++k) acc2[k] = fmaf(v, s2[k * D1_ + j], acc2[k]);
    }
    float y = sBo[0];
    #pragma unroll
    for (int k = 0; k < D2_; ++k) y = fmaf(fmaxf(acc2[k], 0.f), sWo[k], y);

    g_y[row0 + tid] = y;   // t-major, coalesced
}

// ================= out transpose: g_y [T][B] -> out [B][T] =================
__global__ void transpose_out(float* __restrict__ out) {
    __shared__ float tile[32][33];
    const int b0 = blockIdx.x * 32, t0 = blockIdx.y * 32;
    const int tx = threadIdx.x, ty = threadIdx.y;
    for (int i = ty; i < 32; i += 8) {
        int t = t0 + i;
        if (t < T_) tile[i][tx] = g_y[(size_t)t * B_ + b0 + tx];
    }
    __syncthreads();
    for (int i = ty; i < 32; i += 8) {
        int t = t0 + tx;
        if (t < T_) out[(size_t)(b0 + i) * T_ + t] = tile[tx][i];
    }
}

// ---------------- host glue ----------------
extern "C" void kernel_launch(void* const* d_in, const int* in_sizes, int n_in,
                              void* d_out, int out_size)
{
    const float* x      = (const float*)d_in[0];
    const float* w1f_ih = (const float*)d_in[1];
    const float* w1f_hh = (const float*)d_in[2];
    const float* b1f_ih = (const float*)d_in[3];
    const float* b1f_hh = (const float*)d_in[4];
    const float* w1b_ih = (const float*)d_in[5];
    const float* w1b_hh = (const float*)d_in[6];
    const float* b1b_ih = (const float*)d_in[7];
    const float* b1b_hh = (const float*)d_in[8];
    const float* w2f_ih = (const float*)d_in[9];
    const float* w2f_hh = (const float*)d_in[10];
    const float* b2f_ih = (const float*)d_in[11];
    const float* b2f_hh = (const float*)d_in[12];
    const float* w2b_ih = (const float*)d_in[13];
    const float* w2b_hh = (const float*)d_in[14];
    const float* b2b_ih = (const float*)d_in[15];
    const float* b2b_hh = (const float*)d_in[16];
    const float* wd1    = (const float*)d_in[17];
    const float* bd1    = (const float*)d_in[18];
    const float* wd2    = (const float*)d_in[19];
    const float* bd2    = (const float*)d_in[20];
    const float* wo     = (const float*)d_in[21];
    const float* bo     = (const float*)d_in[22];
    float* out = (float*)d_out;

    const int SM1 = (84 * 280 + 3 * 32 * 280 + 32 * 84 * 2 + 32 * 70) * 4;          // 232064
    const int SMX = (144 * 168 + 64 * 144 * 2 + 64 * 168) * 4;                      // 213504
    const int SM2 = (24 * 96 + 2 * 32 * 96 + 32 * 96 + 32 * 24 * 2 + 32 * 21) * 4;  // 54912
    const int SMD = (256 * 43 + 30 * 42 + 30 + 20 * 30 + 20 + 20 + 1) * 4;          // ~51932

    cudaFuncSetAttribute(lstm1_kernel, cudaFuncAttributeMaxDynamicSharedMemorySize, SM1);
    cudaFuncSetAttribute(xg2_kernel,   cudaFuncAttributeMaxDynamicSharedMemorySize, SMX);
    cudaFuncSetAttribute(lstm2_kernel, cudaFuncAttributeMaxDynamicSharedMemorySize, SM2);
    cudaFuncSetAttribute(dense_kernel, cudaFuncAttributeMaxDynamicSharedMemorySize, SMD);

    transpose_x<<<(B_ * T_ * F_ + 255) / 256, 256>>>(x);
    prep_w2<<<(168 * 140 + 255) / 256, 256>>>(w2f_ih, w2b_ih, b2f_ih, b2f_hh, b2b_ih, b2b_hh);

    lstm1_kernel<<<dim3(B_ / 32, 2), 864, SM1>>>(
        w1f_ih, w1f_hh, b1f_ih, b1f_hh,
        w1b_ih, w1b_hh, b1b_ih, b1b_hh);

    xg2_kernel<<<(T_ * B_) / 64, 672, SMX>>>();

    lstm2_kernel<<<dim3(B_ / 32, 2), 384, SM2>>>(w2f_hh, w2b_hh);

    dense_kernel<<<(T_ * B_) / 256, 256, SMD>>>(wd1, bd1, wd2, bd2, wo, bo);

    transpose_out<<<dim3(B_ / 32, (T_ + 31) / 32), dim3(32, 8)>>>(out);
}

// round 8
// speedup vs baseline: 1.1911x; 1.1911x over previous
#include <cuda_runtime.h>
#include <cstdint>

#define B_  2048
#define T_  336
#define F_  10
#define H1_ 70
#define H2_ 21
#define D1_ 30
#define D2_ 20

typedef unsigned long long u64;

// ---------------- scratch (__device__ globals; no allocations) ----------------
__device__ float g_xT [(size_t)T_ * B_ * F_];          // x transposed [T][B][10]
__device__ float g_h1 [(size_t)T_ * B_ * (2*H1_)];     // layer1 out   [T][B][140]
__device__ float g_xg2[(size_t)T_ * B_ * (8*H2_)];     // layer2 input gates [T][B][168] (gate-interleaved)
__device__ float g_h2 [(size_t)T_ * B_ * (2*H2_)];     // layer2 out   [T][B][42]
__device__ float g_y  [(size_t)T_ * B_];               // head out, t-major
__device__ float g_w2t[140 * 168];                     // W2_ih^T packed, both dirs, gate-interleaved
__device__ float g_b2 [168];

// ---------------- packed f32x2 fma ----------------
__device__ __forceinline__ u64 fma2_(u64 a, u64 b, u64 c) {
    u64 d;
    asm("fma.rn.f32x2 %0, %1, %2, %3;" : "=l"(d) : "l"(a), "l"(b), "l"(c));
    return d;
}

// ---------------- activations (accurate fast-math, ~1e-6 rel) ----------------
__device__ __forceinline__ float fsigm(float x) {
    return __fdividef(1.f, 1.f + __expf(-x));
}
__device__ __forceinline__ float ftanh_(float x) {
    return 1.f - 2.f * __fdividef(1.f, 1.f + __expf(2.f * x));
}

// ---------------- transpose x: [B][T][F] -> [T][B][F] (split in halves) ----------------
__global__ void transpose_x(const float* __restrict__ x, int base) {
    int gid = base + blockIdx.x * blockDim.x + threadIdx.x;
    if (gid < B_ * T_ * F_) {
        int f = gid % F_;
        int t = (gid / F_) % T_;
        int b = gid / (F_ * T_);
        g_xT[((size_t)t * B_ + b) * F_ + f] = x[gid];
    }
}

// ---------------- prep: transpose layer-2 input weights to k-major, gate-interleaved ----------------
// Output column jj = dir*84 + 4*h + gate, source row j_src = gate*21 + h.
__global__ void prep_w2(const float* __restrict__ wf, const float* __restrict__ wb,
                        const float* __restrict__ bfi, const float* __restrict__ bfh,
                        const float* __restrict__ bbi, const float* __restrict__ bbh) {
    int i = blockIdx.x * blockDim.x + threadIdx.x;
    if (i < 168 * 140) {
        int jj = i / 140;
        int k  = i % 140;
        int dir = jj / 84, r = jj % 84;
        int h = r / 4, gate = r % 4;
        int j = gate * H2_ + h;
        const float* w = dir ? wb : wf;
        g_w2t[k * 168 + jj] = w[j * 140 + k];
    }
    if (i < 168) {
        int dir = i / 84, r = i % 84;
        int h = r / 4, gate = r % 4;
        int j = gate * H2_ + h;
        g_b2[i] = dir ? (bbi[j] + bbh[j]) : (bfi[j] + bfh[j]);
    }
}

// ================= layer 1: fused-input recurrent LSTM, 2 K-teams, gate-interleaved =================
// block = 32 samples x 1 direction; 576 threads = 2 K-teams x (4 SG x 72 chunks).
// Column jj = 4*h + gate (h=0..69); cols 280..287 zero pad.
__global__ __launch_bounds__(576, 1)
void lstm1_kernel(const float* __restrict__ Wih_f, const float* __restrict__ Whh_f,
                  const float* __restrict__ bih_f, const float* __restrict__ bhh_f,
                  const float* __restrict__ Wih_b, const float* __restrict__ Whh_b,
                  const float* __restrict__ bih_b, const float* __restrict__ bhh_b)
{
    constexpr int I = 10, H = 70, K = 80, KP2 = 82, G = 280, GP = 288;
    constexpr int NJC = 72, TB = 8, NTH = 576, KH = 40;
    extern __shared__ float sm[];
    float* sW = sm;                    // [80][288] k-major, gate-interleaved
    float* gP = sW + K * GP;           // [2][32][288] partial gates
    float* aS = gP + 2 * 32 * GP;      // [32][82] duplicated pairs (float2)
    float* cS = aS + 32 * KP2 * 2;     // [32][70]
    float* sb = cS + 32 * H;           // [288]

    const int dir = blockIdx.y;
    const float* Wih = dir ? Wih_b : Wih_f;
    const float* Whh = dir ? Whh_b : Whh_f;
    const float* bih = dir ? bih_b : bih_f;
    const float* bhh = dir ? bhh_b : bhh_f;
    const int b0  = blockIdx.x * 32;
    const int tid = threadIdx.x;

    for (int idx = tid; idx < K * GP; idx += NTH) {
        int k = idx / GP, jj = idx % GP;
        float v = 0.f;
        if (jj < G) {
            int h = jj / 4, gate = jj % 4;
            int j = gate * H + h;
            v = (k < I) ? Wih[j * I + k] : Whh[j * H + (k - I)];
        }
        sW[idx] = v;
    }
    for (int jj = tid; jj < GP; jj += NTH) {
        float v = 0.f;
        if (jj < G) {
            int h = jj / 4, gate = jj % 4;
            int j = gate * H + h;
            v = bih[j] + bhh[j];
        }
        sb[jj] = v;
    }
    for (int idx = tid; idx < 32 * KP2 * 2; idx += NTH) aS[idx] = 0.f;
    for (int idx = tid; idx < 32 * H; idx += NTH) cS[idx] = 0.f;

    // x staging map: 320 x floats, tid<320 one each (stride-1 dup-pair stores)
    const bool xp = tid < 32 * I;
    const int xb0 = tid / I, xk0 = tid % I;
    // activation map start (element-consecutive; stride NTH=576 -> b+=8, h+=16)
    const int ab0 = tid / H, ah0 = tid % H;

    const int ks = tid / 288;           // K-team
    const int r288 = tid - ks * 288;
    const int sg = r288 / NJC, jc = r288 % NJC;
    const int kbase = ks * KH;
    const u64* arow = ((const u64*)aS) + (size_t)(sg * TB) * KP2;
    const ulonglong2* sWp = (const ulonglong2*)sW;
    ulonglong2* gPd = ((ulonglong2*)(gP + ks * 32 * GP));

    int t = dir ? (T_ - 1) : 0;
    const int tstep = dir ? -1 : 1;
    float xp0 = 0.f;
    if (xp) xp0 = g_xT[((size_t)t * B_ + b0) * I + tid];
    __syncthreads();

    for (int s = 0; s < T_; ++s, t += tstep) {
        // ---- stage x_t as duplicated pairs ----
        if (xp) ((float2*)aS)[xb0 * KP2 + xk0] = make_float2(xp0, xp0);
        __syncthreads();
        if (xp && s + 1 < T_)
            xp0 = g_xT[((size_t)(t + tstep) * B_ + b0) * I + tid];

        // ---- packed matvec partial: gP[ks] = (ks? 0 : bias) + a[krange] @ W[krange] ----
        {
            float4 b4 = make_float4(0.f, 0.f, 0.f, 0.f);
            if (ks == 0) b4 = ((const float4*)sb)[jc];
            ulonglong2 binit = *reinterpret_cast<ulonglong2*>(&b4);
            ulonglong2 acc[TB];
            #pragma unroll
            for (int r = 0; r < TB; ++r) acc[r] = binit;

            #pragma unroll 4
            for (int kk = 0; kk < KH; kk += 2) {
                const int k = kbase + kk;
                ulonglong2 w0 = sWp[k * NJC + jc];
                ulonglong2 w1 = sWp[(k + 1) * NJC + jc];
                #pragma unroll
                for (int r = 0; r < TB; ++r) {
                    ulonglong2 a = *(const ulonglong2*)(arow + r * KP2 + k);
                    acc[r].x = fma2_(a.x, w0.x, acc[r].x);
                    acc[r].y = fma2_(a.x, w0.y, acc[r].y);
                    acc[r].x = fma2_(a.y, w1.x, acc[r].x);
                    acc[r].y = fma2_(a.y, w1.y, acc[r].y);
                }
            }
            #pragma unroll
            for (int r = 0; r < TB; ++r) gPd[(sg * TB + r) * NJC + jc] = acc[r];
        }
        __syncthreads();

        // ---- gates: one float4 per team per elem + state update + h store ----
        {
            float* orow = g_h1 + ((size_t)t * B_ + b0) * (2 * H1_) + dir * H;
            int b = ab0, h = ah0;
            for (int e = tid; e < 32 * H; e += NTH) {
                float4 q0 = ((const float4*)(gP + b * GP))[h];
                float4 q1 = ((const float4*)(gP + 32 * GP + b * GP))[h];
                float gi = q0.x + q1.x;
                float gf = q0.y + q1.y;
                float gg = q0.z + q1.z;
                float go = q0.w + q1.w;
                float c = fsigm(gf) * cS[e] + fsigm(gi) * ftanh_(gg);
                cS[e] = c;
                float hn = fsigm(go) * ftanh_(c);
                ((float2*)aS)[b * KP2 + I + h] = make_float2(hn, hn);
                orow[b * (2 * H1_) + h] = hn;
                b += 8; h += 16; if (h >= H) { h -= H; ++b; }
            }
        }
    }
}

// ================= layer-2 input GEMM: xg2 = h1 @ W2ih^T + biases =================
// block = 96 rows; K=140 (pairs, pitch 142), G=168; TB=12, NSG=8, NJC=42 -> 336 of 352 thr
__global__ __launch_bounds__(352, 1)
void xg2_kernel()
{
    constexpr int BB = 96, K = 140, KP2 = 142, G = 168, NJC = 42, TB = 12;
    extern __shared__ float sm[];
    float* sW = sm;                 // [140][168]
    float* aS = sW + K * G;         // [96][142] duplicated pairs
    float* sb = aS + BB * KP2 * 2;  // [168]
    const int tid = threadIdx.x;
    const size_t row0 = (size_t)blockIdx.x * BB;

    {
        const float4* wsrc = (const float4*)g_w2t;
        float4* wdst = (float4*)sW;
        for (int i = tid; i < K * G / 4; i += 352) wdst[i] = wsrc[i];
    }
    for (int j = tid; j < G; j += 352) sb[j] = g_b2[j];
    {
        const float* src = g_h1 + row0 * K;
        int r = tid / K, c = tid % K;
        for (int q = tid; q < BB * K; q += 352) {
            float v = src[q];
            ((float2*)aS)[r * KP2 + c] = make_float2(v, v);
            r += 2; c += 72; if (c >= K) { c -= K; ++r; }
        }
    }
    __syncthreads();

    if (tid < 336) {
        const int sg = tid / NJC, jc = tid % NJC;
        const u64* arow = ((const u64*)aS) + (size_t)(sg * TB) * KP2;
        const ulonglong2* sWp = (const ulonglong2*)sW;
        float4 b4 = ((const float4*)sb)[jc];
        ulonglong2 binit = *reinterpret_cast<ulonglong2*>(&b4);
        ulonglong2 acc[TB];
        #pragma unroll
        for (int r = 0; r < TB; ++r) acc[r] = binit;

        #pragma unroll 2
        for (int kk = 0; kk < K; kk += 2) {
            ulonglong2 w0 = sWp[kk * NJC + jc];
            ulonglong2 w1 = sWp[(kk + 1) * NJC + jc];
            #pragma unroll
            for (int r = 0; r < TB; ++r) {
                ulonglong2 a = *(const ulonglong2*)(arow + r * KP2 + kk);
                acc[r].x = fma2_(a.x, w0.x, acc[r].x);
                acc[r].y = fma2_(a.x, w0.y, acc[r].y);
                acc[r].x = fma2_(a.y, w1.x, acc[r].x);
                acc[r].y = fma2_(a.y, w1.y, acc[r].y);
            }
        }
        float4* outp = (float4*)(g_xg2 + row0 * G);
        #pragma unroll
        for (int r = 0; r < TB; ++r)
            outp[(sg * TB + r) * NJC + jc] = *reinterpret_cast<float4*>(&acc[r]);
    }
}

// ================= layer 2: recurrent-only LSTM (K=21 pad 24), K-split teams, interleaved =================
// Column jj = 4*h + gate (h=0..20); cols 84..95 zero pad. Input gates arrive pre-interleaved.
__global__ __launch_bounds__(384, 1)
void lstm2_kernel(const float* __restrict__ Whh_f, const float* __restrict__ Whh_b)
{
    constexpr int H = 21, KPAD = 24, KP2 = 24, G = 84, GP = 96;
    constexpr int NJC = 24, TB = 4, NTH = 384, KH = 12;
    extern __shared__ float sm[];
    float* sW = sm;                 // [24][96] gate-interleaved
    float* gS = sW + KPAD * GP;     // [2][32][96] input gates (double-buffered), team0 rmw
    float* gP = gS + 2 * 32 * GP;   // [32][96] team1 partial
    float* aS = gP + 32 * GP;       // [32][24] duplicated pairs
    float* cS = aS + 32 * KP2 * 2;  // [32][21]

    const int dir = blockIdx.y;
    const float* Whh = dir ? Whh_b : Whh_f;
    const int b0  = blockIdx.x * 32;
    const int tid = threadIdx.x;

    for (int idx = tid; idx < KPAD * GP; idx += NTH) {
        int k = idx / GP, jj = idx % GP;
        float v = 0.f;
        if (k < H && jj < G) {
            int h = jj / 4, gate = jj % 4;
            int j = gate * H + h;
            v = Whh[j * H + k];
        }
        sW[idx] = v;
    }
    for (int idx = tid; idx < 32 * KP2 * 2; idx += NTH) aS[idx] = 0.f;
    for (int idx = tid; idx < 32 * H; idx += NTH) cS[idx] = 0.f;

    const int gb0 = tid / 21, gc0 = tid % 21;
    const int i1 = tid + NTH;
    const int gb1 = i1 / 21, gc1 = i1 % 21;
    const bool v1 = i1 < 672;
    const int ab0 = tid / H, ah0 = tid % H;

    const int ks = tid / 192;
    const int r192 = tid - ks * 192;
    const int sg = r192 / NJC, jc = r192 % NJC;
    const int kbase = ks * KH;
    const u64* arow = ((const u64*)aS) + (size_t)(sg * TB) * KP2;
    const ulonglong2* sWp = (const ulonglong2*)sW;

    int t = dir ? (T_ - 1) : 0;
    const int tstep = dir ? -1 : 1;
    float4 gp0, gp1;
    {
        const float4* src = (const float4*)(g_xg2 + ((size_t)t * B_ + b0) * 168 + dir * 84);
        gp0 = src[gb0 * 42 + gc0];
        if (v1) gp1 = src[gb1 * 42 + gc1];
    }
    __syncthreads();

    for (int s = 0; s < T_; ++s, t += tstep) {
        const int p = s & 1;
        float* gSb = gS + p * 32 * GP;
        float4* gSd = (float4*)gSb;
        gSd[gb0 * 24 + gc0] = gp0;
        if (v1) gSd[gb1 * 24 + gc1] = gp1;
        __syncthreads();
        if (s + 1 < T_) {
            const float4* src = (const float4*)(g_xg2 + ((size_t)(t + tstep) * B_ + b0) * 168 + dir * 84);
            gp0 = src[gb0 * 42 + gc0];
            if (v1) gp1 = src[gb1 * 42 + gc1];
        }
        {
            ulonglong2* dst = (ulonglong2*)(ks ? gP : gSb);
            ulonglong2 acc[TB];
            #pragma unroll
            for (int r = 0; r < TB; ++r) {
                if (ks == 0) acc[r] = ((const ulonglong2*)gSb)[(sg * TB + r) * NJC + jc];
                else         acc[r] = make_ulonglong2(0ull, 0ull);
            }
            #pragma unroll
            for (int kk = 0; kk < KH; kk += 2) {
                const int k = kbase + kk;
                ulonglong2 w0 = sWp[k * NJC + jc];
                ulonglong2 w1 = sWp[(k + 1) * NJC + jc];
                #pragma unroll
                for (int r = 0; r < TB; ++r) {
                    ulonglong2 a = *(const ulonglong2*)(arow + r * KP2 + k);
                    acc[r].x = fma2_(a.x, w0.x, acc[r].x);
                    acc[r].y = fma2_(a.x, w0.y, acc[r].y);
                    acc[r].x = fma2_(a.y, w1.x, acc[r].x);
                    acc[r].y = fma2_(a.y, w1.y, acc[r].y);
                }
            }
            #pragma unroll
            for (int r = 0; r < TB; ++r)
                dst[(sg * TB + r) * NJC + jc] = acc[r];
        }
        __syncthreads();

        {
            float* orow = g_h2 + ((size_t)t * B_ + b0) * (2 * H2_) + dir * H;
            int b = ab0, h = ah0;
            for (int e = tid; e < 32 * H; e += NTH) {
                float4 q0 = ((const float4*)(gSb + b * GP))[h];
                float4 q1 = ((const float4*)(gP + b * GP))[h];
                float gi = q0.x + q1.x;
                float gf = q0.y + q1.y;
                float gg = q0.z + q1.z;
                float go = q0.w + q1.w;
                float c = fsigm(gf) * cS[e] + fsigm(gi) * ftanh_(gg);
                cS[e] = c;
                float hn = fsigm(go) * ftanh_(c);
                ((float2*)aS)[b * KP2 + h] = make_float2(hn, hn);
                orow[b * (2 * H2_) + h] = hn;
                b += 18; h += 6; if (h >= H) { h -= H; ++b; }
            }
        }
    }
}

// ================= dense head (smem-staged rows, padded pitch) =================
__global__ __launch_bounds__(256)
void dense_kernel(const float* __restrict__ wd1, const float* __restrict__ bd1,
                  const float* __restrict__ wd2, const float* __restrict__ bd2,
                  const float* __restrict__ wo,  const float* __restrict__ bo)
{
    constexpr int IN = 2 * H2_;   // 42
    constexpr int INP = 43;       // padded pitch (odd -> conflict-free)
    extern __shared__ float sm[];
    float* sIn = sm;                    // [256][43]
    float* s1  = sIn + 256 * INP;       // [30][42]
    float* sb1 = s1 + D1_ * IN;
    float* s2  = sb1 + D1_;             // [20][30]
    float* sb2 = s2 + D2_ * D1_;
    float* sWo = sb2 + D2_;
    float* sBo = sWo + D2_;

    const int tid = threadIdx.x;
    const size_t row0 = (size_t)blockIdx.x * 256;

    {
        const float* src = g_h2 + row0 * IN;
        int r = tid / IN, c = tid % IN;
        for (int q = tid; q < 256 * IN; q += 256) {
            sIn[r * INP + c] = src[q];
            r += 6; c += 4; if (c >= IN) { c -= IN; ++r; }
        }
    }
    for (int i = tid; i < D1_ * IN; i += 256) s1[i] = wd1[i];
    for (int i = tid; i < D2_ * D1_; i += 256) s2[i] = wd2[i];
    if (tid < D1_) sb1[tid] = bd1[tid];
    if (tid < D2_) { sb2[tid] = bd2[tid]; sWo[tid] = wo[tid]; }
    if (tid == 0) sBo[0] = bo[0];
    __syncthreads();

    const float* in = sIn + tid * INP;
    float acc2[D2_];
    #pragma unroll
    for (int k = 0; k < D2_; ++k) acc2[k] = sb2[k];
    #pragma unroll 2
    for (int j = 0; j < D1_; ++j) {
        float v = sb1[j];
        #pragma unroll
        for (int k = 0; k < IN; ++k) v = fmaf(in[k], s1[j * IN + k], v);
        v = fmaxf(v, 0.f);
        #pragma unroll
        for (int k = 0; k < D2_; ++k) acc2[k] = fmaf(v, s2[k * D1_ + j], acc2[k]);
    }
    float y = sBo[0];
    #pragma unroll
    for (int k = 0; k < D2_; ++k) y = fmaf(fmaxf(acc2[k], 0.f), sWo[k], y);

    g_y[row0 + tid] = y;   // t-major, coalesced
}

// ================= out transpose: g_y [T][B] -> out [B][T] =================
__global__ void transpose_out(float* __restrict__ out) {
    __shared__ float tile[32][33];
    const int b0 = blockIdx.x * 32, t0 = blockIdx.y * 32;
    const int tx = threadIdx.x, ty = threadIdx.y;
    for (int i = ty; i < 32; i += 8) {
        int t = t0 + i;
        if (t < T_) tile[i][tx] = g_y[(size_t)t * B_ + b0 + tx];
    }
    __syncthreads();
    for (int i = ty; i < 32; i += 8) {
        int t = t0 + tx;
        if (t < T_) out[(size_t)(b0 + i) * T_ + t] = tile[tx][i];
    }
}

// ---------------- host glue ----------------
extern "C" void kernel_launch(void* const* d_in, const int* in_sizes, int n_in,
                              void* d_out, int out_size)
{
    const float* x      = (const float*)d_in[0];
    const float* w1f_ih = (const float*)d_in[1];
    const float* w1f_hh = (const float*)d_in[2];
    const float* b1f_ih = (const float*)d_in[3];
    const float* b1f_hh = (const float*)d_in[4];
    const float* w1b_ih = (const float*)d_in[5];
    const float* w1b_hh = (const float*)d_in[6];
    const float* b1b_ih = (const float*)d_in[7];
    const float* b1b_hh = (const float*)d_in[8];
    const float* w2f_ih = (const float*)d_in[9];
    const float* w2f_hh = (const float*)d_in[10];
    const float* b2f_ih = (const float*)d_in[11];
    const float* b2f_hh = (const float*)d_in[12];
    const float* w2b_ih = (const float*)d_in[13];
    const float* w2b_hh = (const float*)d_in[14];
    const float* b2b_ih = (const float*)d_in[15];
    const float* b2b_hh = (const float*)d_in[16];
    const float* wd1    = (const float*)d_in[17];
    const float* bd1    = (const float*)d_in[18];
    const float* wd2    = (const float*)d_in[19];
    const float* bd2    = (const float*)d_in[20];
    const float* wo     = (const float*)d_in[21];
    const float* bo     = (const float*)d_in[22];
    float* out = (float*)d_out;

    const int SM1 = (80 * 288 + 2 * 32 * 288 + 32 * 82 * 2 + 32 * 70 + 288) * 4;        // 196992
    const int SMX = (140 * 168 + 96 * 142 * 2 + 168) * 4;                               // 203808
    const int SM2 = (24 * 96 + 2 * 32 * 96 + 32 * 96 + 32 * 24 * 2 + 32 * 21) * 4;      // 54912
    const int SMD = (256 * 43 + 30 * 42 + 30 + 20 * 30 + 20 + 20 + 1) * 4;              // ~51932

    cudaFuncSetAttribute(lstm1_kernel, cudaFuncAttributeMaxDynamicSharedMemorySize, SM1);
    cudaFuncSetAttribute(xg2_kernel,   cudaFuncAttributeMaxDynamicSharedMemorySize, SMX);
    cudaFuncSetAttribute(lstm2_kernel, cudaFuncAttributeMaxDynamicSharedMemorySize, SM2);
    cudaFuncSetAttribute(dense_kernel, cudaFuncAttributeMaxDynamicSharedMemorySize, SMD);

    const int TOT = B_ * T_ * F_;
    const int HALF = (TOT + 1) / 2;

    // launches 1-3 (keeps lstm1 as the 4th launch -> profiled by ncu)
    transpose_x<<<(HALF + 255) / 256, 256>>>(x, 0);
    transpose_x<<<(TOT - HALF + 255) / 256, 256>>>(x, HALF);
    prep_w2<<<(168 * 140 + 255) / 256, 256>>>(w2f_ih, w2b_ih, b2f_ih, b2f_hh, b2b_ih, b2b_hh);

    // launch 4: the dominant kernel
    lstm1_kernel<<<dim3(B_ / 32, 2), 576, SM1>>>(
        w1f_ih, w1f_hh, b1f_ih, b1f_hh,
        w1b_ih, w1b_hh, b1b_ih, b1b_hh);

    xg2_kernel<<<(T_ * B_) / 96, 352, SMX>>>();

    lstm2_kernel<<<dim3(B_ / 32, 2), 384, SM2>>>(w2f_hh, w2b_hh);

    dense_kernel<<<(T_ * B_) / 256, 256, SMD>>>(wd1, bd1, wd2, bd2, wo, bo);

    transpose_out<<<dim3(B_ / 32, (T_ + 31) / 32), dim3(32, 8)>>>(out);
}